// round 9
// baseline (speedup 1.0000x reference)
#include <cuda_runtime.h>

#define N_NODES 16384
#define A_ANCH  256
#define D_LAT   32

// Precomputed (1/A) * (anchor_emb @ W1)  and  c[j] = b[j] + (1/A)*sum_a (embeds[a] @ W2)[j]
__device__ float g_M[A_ANCH * D_LAT];   // 32 KB
__device__ float g_c[D_LAT];

// ---------------------------------------------------------------------------
// Kernel 1: precompute g_M and g_c. Grid = 9 blocks x 256 threads.
// ---------------------------------------------------------------------------
__global__ __launch_bounds__(256) void precompute_kernel(
    const float* __restrict__ embeds,
    const float* __restrict__ W,       // [64,32]: W1 rows 0..31, W2 rows 32..63
    const float* __restrict__ b,       // [32]
    const int*   __restrict__ anchor_ids)
{
    __shared__ float Wsh[D_LAT * D_LAT];
    __shared__ float esh[32][32];
    __shared__ float ssh[D_LAT];

    const int t   = threadIdx.x;
    const int blk = blockIdx.x;
    const int j   = t & 31;

    if (blk < 8) {
        #pragma unroll
        for (int i = t; i < D_LAT * D_LAT; i += 256) Wsh[i] = W[i];
        for (int r = t >> 5; r < 32; r += 8) {
            int id = anchor_ids[blk * 32 + r];
            esh[r][j] = embeds[id * D_LAT + j];
        }
        __syncthreads();
        for (int r = t >> 5; r < 32; r += 8) {
            float acc = 0.f;
            #pragma unroll
            for (int d = 0; d < D_LAT; d++) acc += esh[r][d] * Wsh[d * D_LAT + j];
            g_M[(blk * 32 + r) * D_LAT + j] = acc * (1.0f / 256.0f);
        }
    } else {
        #pragma unroll
        for (int i = t; i < D_LAT * D_LAT; i += 256) Wsh[i] = W[D_LAT * D_LAT + i];
        if (t < D_LAT) ssh[t] = 0.f;
        __syncthreads();
        {
            int grp = t >> 5;
            float part = 0.f;
            #pragma unroll 4
            for (int i = 0; i < 32; i++)
                part += embeds[(grp * 32 + i) * D_LAT + j];
            atomicAdd(&ssh[j], part);
        }
        __syncthreads();
        if (t < D_LAT) {
            float acc = 0.f;
            #pragma unroll
            for (int d = 0; d < D_LAT; d++) acc += ssh[d] * Wsh[d * D_LAT + t];
            g_c[t] = b[t] + acc * (1.0f / 256.0f);
        }
    }
}

// ---------------------------------------------------------------------------
// Kernel 2: out[n,:] = sum_a dists[a,n] * g_M[a,:] + g_c
//
// R2's proven inner loop: 256 thr = 16 slots (4n) x 2 halves (16 cols)
// x 8 a-groups; thread tile 4n x 16col = 32 packed f32x2 accs.
// New: PDL (prefetch before gridsync), single-round reduction (2 barriers),
// all-thread coalesced epilogue (u64 = 2 adjacent cols, direct store).
// Dyn smem 67.6 KB; 2 blocks/SM; grid 256 = 1 wave.
// ---------------------------------------------------------------------------
#define SMEM_U64 8448   // 8 groups * 32 k * 33 pad

__global__ __launch_bounds__(256, 2) void pnn_main_kernel(
    const float* __restrict__ dists,   // [A, N]
    float*       __restrict__ out)     // [N, D]
{
    extern __shared__ __align__(16) unsigned long long sh[];
    float* Msh = (float*)sh;

    const int t      = threadIdx.x;
    const int slot   = t & 15;         // n-slot
    const int half   = (t >> 4) & 1;   // column half
    const int group  = t >> 5;         // a-group == warp
    const int lane32 = t & 31;         // slot + 16*half
    const int n0     = blockIdx.x * 64 + slot * 4;
    const int a0     = group * 32;

    // ---- dists prefetches first (overlap precompute via PDL) ----
    const float* dp = dists + (size_t)a0 * N_NODES + n0;
    float4 pf[4];
    #pragma unroll
    for (int i = 0; i < 4; i++)
        pf[i] = *(const float4*)(dp + (size_t)i * N_NODES);

    cudaGridDependencySynchronize();

    // ---- load M (32 KB) into shared ----
    {
        const float4* src = (const float4*)g_M;
        float4*       dst = (float4*)Msh;
        #pragma unroll
        for (int i = 0; i < 8; i++) dst[t + 256 * i] = src[t + 256 * i];
    }
    __syncthreads();

    unsigned long long acc[32];        // [n 0..3][k 0..7], k = col-pair in half
    #pragma unroll
    for (int i = 0; i < 32; i++) acc[i] = 0ULL;

    const float* mrow = Msh + a0 * D_LAT + half * 16;

    #pragma unroll 2
    for (int it = 0; it < 32; it += 4) {
        #pragma unroll
        for (int u = 0; u < 4; u++) {
            float4 d = pf[u];
            int nx = (it + u + 4) & 31;            // wrapped (unused on last round)
            pf[u] = *(const float4*)(dp + (size_t)nx * N_NODES);

            unsigned long long dd0, dd1, dd2, dd3;
            asm("mov.b64 %0,{%1,%1};" : "=l"(dd0) : "f"(d.x));
            asm("mov.b64 %0,{%1,%1};" : "=l"(dd1) : "f"(d.y));
            asm("mov.b64 %0,{%1,%1};" : "=l"(dd2) : "f"(d.z));
            asm("mov.b64 %0,{%1,%1};" : "=l"(dd3) : "f"(d.w));

            const ulonglong2* mp = (const ulonglong2*)(mrow + (it + u) * D_LAT);
            ulonglong2 m0 = mp[0], m1 = mp[1], m2 = mp[2], m3 = mp[3];

            #define FMA8(nn, dd)                                                          \
                asm("fma.rn.f32x2 %0,%1,%2,%0;" : "+l"(acc[(nn)*8+0]) : "l"(dd), "l"(m0.x)); \
                asm("fma.rn.f32x2 %0,%1,%2,%0;" : "+l"(acc[(nn)*8+1]) : "l"(dd), "l"(m0.y)); \
                asm("fma.rn.f32x2 %0,%1,%2,%0;" : "+l"(acc[(nn)*8+2]) : "l"(dd), "l"(m1.x)); \
                asm("fma.rn.f32x2 %0,%1,%2,%0;" : "+l"(acc[(nn)*8+3]) : "l"(dd), "l"(m1.y)); \
                asm("fma.rn.f32x2 %0,%1,%2,%0;" : "+l"(acc[(nn)*8+4]) : "l"(dd), "l"(m2.x)); \
                asm("fma.rn.f32x2 %0,%1,%2,%0;" : "+l"(acc[(nn)*8+5]) : "l"(dd), "l"(m2.y)); \
                asm("fma.rn.f32x2 %0,%1,%2,%0;" : "+l"(acc[(nn)*8+6]) : "l"(dd), "l"(m3.x)); \
                asm("fma.rn.f32x2 %0,%1,%2,%0;" : "+l"(acc[(nn)*8+7]) : "l"(dd), "l"(m3.y));

            FMA8(0, dd0)
            FMA8(1, dd1)
            FMA8(2, dd2)
            FMA8(3, dd3)
            #undef FMA8
        }
    }

    // ---- single-round reduction over the 8 a-groups ----
    // partials: sh[(group*32 + i)*33 + lane32], i = nn*8 + k
    __syncthreads();
    #pragma unroll
    for (int i = 0; i < 32; i++)
        sh[(group * 32 + i) * 33 + lane32] = acc[i];
    __syncthreads();

    // ---- epilogue: each thread produces 4 final u64 (= 2 adjacent cols) ----
    const unsigned long long* c64 = (const unsigned long long*)g_c;
    const int bn0 = blockIdx.x * 64;

    #pragma unroll
    for (int h = 0; h < 4; h++) {
        const int o       = t + h * 256;      // 0..1023
        const int n_local = o >> 4;           // 0..63
        const int kcol    = o & 15;           // u64 col-pair 0..15
        const int eslot   = n_local >> 2;
        const int nn      = n_local & 3;
        const int ehalf   = kcol >> 3;
        const int k       = kcol & 7;
        const int base    = (nn * 8 + k) * 33 + eslot + 16 * ehalf;

        unsigned long long r = sh[base];
        #pragma unroll
        for (int g = 1; g < 8; g++)
            asm("add.rn.f32x2 %0,%0,%1;" : "+l"(r) : "l"(sh[g * 1056 + base]));
        asm("add.rn.f32x2 %0,%0,%1;" : "+l"(r) : "l"(c64[kcol]));

        *(unsigned long long*)(out + (size_t)(bn0 + n_local) * D_LAT + kcol * 2) = r;
    }
}

extern "C" void kernel_launch(void* const* d_in, const int* in_sizes, int n_in,
                              void* d_out, int out_size)
{
    const float* embeds     = (const float*)d_in[0];
    const float* dists      = (const float*)d_in[1];
    const float* W_hidden   = (const float*)d_in[2];
    const float* b_hidden   = (const float*)d_in[3];
    const int*   anchor_ids = (const int*)  d_in[4];
    float*       out        = (float*)d_out;

    cudaFuncSetAttribute(pnn_main_kernel,
                         cudaFuncAttributeMaxDynamicSharedMemorySize,
                         SMEM_U64 * 8);

    precompute_kernel<<<9, 256>>>(embeds, W_hidden, b_hidden, anchor_ids);

    cudaLaunchConfig_t cfg = {};
    cfg.gridDim  = dim3(N_NODES / 64, 1, 1);
    cfg.blockDim = dim3(256, 1, 1);
    cfg.dynamicSmemBytes = SMEM_U64 * 8;
    cfg.stream = 0;
    cudaLaunchAttribute attr[1];
    attr[0].id = cudaLaunchAttributeProgrammaticStreamSerialization;
    attr[0].val.programmaticStreamSerializationAllowed = 1;
    cfg.attrs = attr;
    cfg.numAttrs = 1;

    cudaError_t e = cudaLaunchKernelEx(&cfg, pnn_main_kernel, dists, out);
    if (e != cudaSuccess) {
        pnn_main_kernel<<<N_NODES / 64, 256, SMEM_U64 * 8>>>(dists, out);
    }
}

// round 10
// speedup vs baseline: 1.0133x; 1.0133x over previous
#include <cuda_runtime.h>

#define N_NODES 16384
#define A_ANCH  256
#define D_LAT   32

// Precomputed (1/A) * (anchor_emb @ W1)  and  c[j] = b[j] + (1/A)*sum_a (embeds[a] @ W2)[j]
__device__ float g_M[A_ANCH * D_LAT];   // 32 KB
__device__ float g_c[D_LAT];

// ---------------------------------------------------------------------------
// Kernel 1: precompute g_M and g_c. Grid = 9 blocks x 256 threads.
// ---------------------------------------------------------------------------
__global__ __launch_bounds__(256) void precompute_kernel(
    const float* __restrict__ embeds,
    const float* __restrict__ W,       // [64,32]: W1 rows 0..31, W2 rows 32..63
    const float* __restrict__ b,       // [32]
    const int*   __restrict__ anchor_ids)
{
    __shared__ float Wsh[D_LAT * D_LAT];
    __shared__ float esh[32][32];
    __shared__ float ssh[D_LAT];

    const int t   = threadIdx.x;
    const int blk = blockIdx.x;
    const int j   = t & 31;

    if (blk < 8) {
        #pragma unroll
        for (int i = t; i < D_LAT * D_LAT; i += 256) Wsh[i] = W[i];
        for (int r = t >> 5; r < 32; r += 8) {
            int id = anchor_ids[blk * 32 + r];
            esh[r][j] = embeds[id * D_LAT + j];
        }
        __syncthreads();
        for (int r = t >> 5; r < 32; r += 8) {
            float acc = 0.f;
            #pragma unroll
            for (int d = 0; d < D_LAT; d++) acc += esh[r][d] * Wsh[d * D_LAT + j];
            g_M[(blk * 32 + r) * D_LAT + j] = acc * (1.0f / 256.0f);
        }
    } else {
        #pragma unroll
        for (int i = t; i < D_LAT * D_LAT; i += 256) Wsh[i] = W[D_LAT * D_LAT + i];
        if (t < D_LAT) ssh[t] = 0.f;
        __syncthreads();
        {
            int grp = t >> 5;
            float part = 0.f;
            #pragma unroll 4
            for (int i = 0; i < 32; i++)
                part += embeds[(grp * 32 + i) * D_LAT + j];
            atomicAdd(&ssh[j], part);
        }
        __syncthreads();
        if (t < D_LAT) {
            float acc = 0.f;
            #pragma unroll
            for (int d = 0; d < D_LAT; d++) acc += ssh[d] * Wsh[d * D_LAT + t];
            g_c[t] = b[t] + acc * (1.0f / 256.0f);
        }
    }
}

// ---------------------------------------------------------------------------
// Kernel 2: EXACT R2 kernel (measured 12.26us, regs=126) + PDL prefetch.
// Block = 256 threads = 16 n-slots x 2 col-halves x 8 a-groups.
//   - thread tile 4n x 16col (32 packed f32x2 accs)
//   - static 32 KB smem (M, then tree reduction)
//   - dists LDG.128 prefetch depth 4, hoisted above the PDL grid sync
// Grid 256 x 64n, 2 blocks/SM.
// ---------------------------------------------------------------------------
__global__ __launch_bounds__(256, 2) void pnn_main_kernel(
    const float* __restrict__ dists,   // [A, N]
    float*       __restrict__ out)     // [N, D]
{
    __shared__ __align__(16) unsigned long long sh[4096];   // 32 KB
    float* Msh = (float*)sh;

    const int t = threadIdx.x;

    const int slot  = t & 15;          // n-slot within block
    const int half  = (t >> 4) & 1;    // column half
    const int group = t >> 5;          // a-group == warp id
    const int n0    = blockIdx.x * 64 + slot * 4;
    const int a0    = group * 32;

    // ---- dists prefetches first: independent of the precompute kernel ----
    const float* dp = dists + (size_t)a0 * N_NODES + n0;
    float4 pf[4];
    #pragma unroll
    for (int i = 0; i < 4; i++)
        pf[i] = *(const float4*)(dp + (size_t)i * N_NODES);

    // ---- wait for precompute results (PDL) ----
    cudaGridDependencySynchronize();

    // load M (32 KB) into shared
    {
        const float4* src = (const float4*)g_M;
        float4*       dst = (float4*)Msh;
        #pragma unroll
        for (int i = 0; i < 8; i++) dst[t + 256 * i] = src[t + 256 * i];
    }
    __syncthreads();

    unsigned long long acc[32];
    #pragma unroll
    for (int i = 0; i < 32; i++) acc[i] = 0ULL;

    const float* mrow = Msh + a0 * D_LAT + half * 16;

    #pragma unroll 2
    for (int it = 0; it < 32; it += 4) {
        #pragma unroll
        for (int u = 0; u < 4; u++) {
            float4 d = pf[u];
            int nx = (it + u + 4) & 31;            // wrapped (unused on last round)
            pf[u] = *(const float4*)(dp + (size_t)nx * N_NODES);

            unsigned long long dd0, dd1, dd2, dd3;
            asm("mov.b64 %0,{%1,%1};" : "=l"(dd0) : "f"(d.x));
            asm("mov.b64 %0,{%1,%1};" : "=l"(dd1) : "f"(d.y));
            asm("mov.b64 %0,{%1,%1};" : "=l"(dd2) : "f"(d.z));
            asm("mov.b64 %0,{%1,%1};" : "=l"(dd3) : "f"(d.w));

            const ulonglong2* mp = (const ulonglong2*)(mrow + (it + u) * D_LAT);
            ulonglong2 m0 = mp[0], m1 = mp[1], m2 = mp[2], m3 = mp[3];

            #define FMA8(nn, dd)                                                          \
                asm("fma.rn.f32x2 %0,%1,%2,%0;" : "+l"(acc[(nn)*8+0]) : "l"(dd), "l"(m0.x)); \
                asm("fma.rn.f32x2 %0,%1,%2,%0;" : "+l"(acc[(nn)*8+1]) : "l"(dd), "l"(m0.y)); \
                asm("fma.rn.f32x2 %0,%1,%2,%0;" : "+l"(acc[(nn)*8+2]) : "l"(dd), "l"(m1.x)); \
                asm("fma.rn.f32x2 %0,%1,%2,%0;" : "+l"(acc[(nn)*8+3]) : "l"(dd), "l"(m1.y)); \
                asm("fma.rn.f32x2 %0,%1,%2,%0;" : "+l"(acc[(nn)*8+4]) : "l"(dd), "l"(m2.x)); \
                asm("fma.rn.f32x2 %0,%1,%2,%0;" : "+l"(acc[(nn)*8+5]) : "l"(dd), "l"(m2.y)); \
                asm("fma.rn.f32x2 %0,%1,%2,%0;" : "+l"(acc[(nn)*8+6]) : "l"(dd), "l"(m3.x)); \
                asm("fma.rn.f32x2 %0,%1,%2,%0;" : "+l"(acc[(nn)*8+7]) : "l"(dd), "l"(m3.y));

            FMA8(0, dd0)
            FMA8(1, dd1)
            FMA8(2, dd2)
            FMA8(3, dd3)
            #undef FMA8
        }
    }

    // ---- log2 tree reduction over the 8 a-groups ----
    __syncthreads();   // done reading M; sh is reusable

    #pragma unroll
    for (int s = 128; s >= 32; s >>= 1) {
        if (t >= s && t < 2 * s) {
            #pragma unroll
            for (int i = 0; i < 32; i++) sh[i * s + (t - s)] = acc[i];
        }
        __syncthreads();
        if (t < s) {
            #pragma unroll
            for (int i = 0; i < 32; i++)
                asm("add.rn.f32x2 %0,%0,%1;" : "+l"(acc[i]) : "l"(sh[i * s + t]));
        }
        __syncthreads();
    }

    // ---- epilogue: threads 0..31 hold final sums for the whole block ----
    if (t < 32) {
        const unsigned long long* c64 = (const unsigned long long*)g_c;
        unsigned long long cc[8];
        #pragma unroll
        for (int k = 0; k < 8; k++) cc[k] = c64[half * 8 + k];
        #pragma unroll
        for (int i = 0; i < 32; i++)
            asm("add.rn.f32x2 %0,%0,%1;" : "+l"(acc[i]) : "l"(cc[i & 7]));

        #pragma unroll
        for (int n = 0; n < 4; n++) {
            ulonglong2* op = (ulonglong2*)(out + (size_t)(n0 + n) * D_LAT + half * 16);
            #pragma unroll
            for (int j = 0; j < 4; j++) {
                ulonglong2 v;
                v.x = acc[n * 8 + 2 * j];
                v.y = acc[n * 8 + 2 * j + 1];
                op[j] = v;
            }
        }
    }
}

extern "C" void kernel_launch(void* const* d_in, const int* in_sizes, int n_in,
                              void* d_out, int out_size)
{
    const float* embeds     = (const float*)d_in[0];
    const float* dists      = (const float*)d_in[1];
    const float* W_hidden   = (const float*)d_in[2];
    const float* b_hidden   = (const float*)d_in[3];
    const int*   anchor_ids = (const int*)  d_in[4];
    float*       out        = (float*)d_out;

    precompute_kernel<<<9, 256>>>(embeds, W_hidden, b_hidden, anchor_ids);

    cudaLaunchConfig_t cfg = {};
    cfg.gridDim  = dim3(N_NODES / 64, 1, 1);
    cfg.blockDim = dim3(256, 1, 1);
    cfg.dynamicSmemBytes = 0;
    cfg.stream = 0;
    cudaLaunchAttribute attr[1];
    attr[0].id = cudaLaunchAttributeProgrammaticStreamSerialization;
    attr[0].val.programmaticStreamSerializationAllowed = 1;
    cfg.attrs = attr;
    cfg.numAttrs = 1;

    cudaError_t e = cudaLaunchKernelEx(&cfg, pnn_main_kernel, dists, out);
    if (e != cudaSuccess) {
        pnn_main_kernel<<<N_NODES / 64, 256>>>(dists, out);
    }
}

// round 11
// speedup vs baseline: 1.0429x; 1.0292x over previous
#include <cuda_runtime.h>
#include <cstdint>

#define N_NODES 16384
#define A_ANCH  256
#define D_LAT   32

// B fragments for mma.m16n8k8.tf32, fragment order, pre-split hi/lo:
//   g_Bfrag[((ks*4 + nt)*32 + lane)] = (b0_hi, b1_hi, b0_lo, b1_lo)
// b0 = Mscaled[ks*8 + lane%4][nt*8 + lane/4], b1 = +4 k-row.
__device__ float4 g_Bfrag[32 * 4 * 32];   // 64 KB
__device__ float  g_c[D_LAT];

// ---------------------------------------------------------------------------
// Kernel 1: precompute B fragments + c (validated in R8).
// ---------------------------------------------------------------------------
__global__ __launch_bounds__(256) void precompute_kernel(
    const float* __restrict__ embeds,
    const float* __restrict__ W,
    const float* __restrict__ b,
    const int*   __restrict__ anchor_ids)
{
    __shared__ float Wsh[D_LAT * D_LAT];
    __shared__ float esh[32][32];
    __shared__ float Ms[32][33];
    __shared__ float ssh[D_LAT];

    const int t   = threadIdx.x;
    const int blk = blockIdx.x;
    const int j   = t & 31;

    if (blk < 8) {
        #pragma unroll
        for (int i = t; i < D_LAT * D_LAT; i += 256) Wsh[i] = W[i];
        for (int r = t >> 5; r < 32; r += 8) {
            int id = anchor_ids[blk * 32 + r];
            esh[r][j] = embeds[id * D_LAT + j];
        }
        __syncthreads();
        for (int r = t >> 5; r < 32; r += 8) {
            float acc = 0.f;
            #pragma unroll
            for (int d = 0; d < D_LAT; d++) acc += esh[r][d] * Wsh[d * D_LAT + j];
            Ms[r][j] = acc * (1.0f / 256.0f);
        }
        __syncthreads();
        #pragma unroll
        for (int i = 0; i < 2; i++) {
            int idx  = t + 256 * i;
            int lane = idx & 31;
            int nt   = (idx >> 5) & 3;
            int kl   = (idx >> 7) & 3;
            int krow = kl * 8 + (lane & 3);
            int col  = nt * 8 + (lane >> 2);
            float b0 = Ms[krow][col];
            float b1 = Ms[krow + 4][col];
            unsigned h0, h1, l0, l1;
            asm("cvt.rna.tf32.f32 %0, %1;" : "=r"(h0) : "f"(b0));
            asm("cvt.rna.tf32.f32 %0, %1;" : "=r"(h1) : "f"(b1));
            float r0 = b0 - __uint_as_float(h0);
            float r1 = b1 - __uint_as_float(h1);
            asm("cvt.rna.tf32.f32 %0, %1;" : "=r"(l0) : "f"(r0));
            asm("cvt.rna.tf32.f32 %0, %1;" : "=r"(l1) : "f"(r1));
            int ks = blk * 4 + kl;
            g_Bfrag[(ks * 4 + nt) * 32 + lane] =
                make_float4(__uint_as_float(h0), __uint_as_float(h1),
                            __uint_as_float(l0), __uint_as_float(l1));
        }
    } else {
        #pragma unroll
        for (int i = t; i < D_LAT * D_LAT; i += 256) Wsh[i] = W[D_LAT * D_LAT + i];
        if (t < D_LAT) ssh[t] = 0.f;
        __syncthreads();
        {
            int grp = t >> 5;
            float part = 0.f;
            #pragma unroll 4
            for (int i = 0; i < 32; i++)
                part += embeds[(grp * 32 + i) * D_LAT + j];
            atomicAdd(&ssh[j], part);
        }
        __syncthreads();
        if (t < D_LAT) {
            float acc = 0.f;
            #pragma unroll
            for (int d = 0; d < D_LAT; d++) acc += ssh[d] * Wsh[d * D_LAT + t];
            g_c[t] = b[t] + acc * (1.0f / 256.0f);
        }
    }
}

// ---------------------------------------------------------------------------
// Kernel 2: tensor GEMM out = dists^T @ M + c, mma.m16n8k8.tf32, 3-term split.
// 256 thr = 8 warps = 4 row-warps x 2 k-groups (128 k each, 16 ksteps/warp).
// Block covers 64 rows; grid 256. K-group partials merged via 8 KB smem.
// ---------------------------------------------------------------------------
#define MMA(AC, A0, A1, A2, A3, B0, B1)                                       \
    asm("mma.sync.aligned.m16n8k8.row.col.f32.tf32.tf32.f32 "                 \
        "{%0,%1,%2,%3},{%4,%5,%6,%7},{%8,%9},{%0,%1,%2,%3};"                  \
        : "+f"(AC[0]), "+f"(AC[1]), "+f"(AC[2]), "+f"(AC[3])                  \
        : "r"(A0), "r"(A1), "r"(A2), "r"(A3), "r"(B0), "r"(B1));

__global__ __launch_bounds__(256) void pnn_mma_kernel(
    const float* __restrict__ dists,   // [A, N]
    float*       __restrict__ out)     // [N, 32]
{
    __shared__ float red[4][32][16];   // 8 KB: k-group-1 partials

    const int t     = threadIdx.x;
    const int lane  = t & 31;
    const int w     = t >> 5;
    const int rtile = w & 3;
    const int kg    = w >> 2;          // 0 or 1
    const int n0    = blockIdx.x * 64 + rtile * 16;

    const int rowA = n0 + (lane >> 2);
    const int colA = lane & 3;
    // k-group kg covers global k rows [kg*128, kg*128+128)
    const float* pa = dists + (size_t)(kg * 128 + colA) * N_NODES + rowA;
    const size_t N4 = 4 * (size_t)N_NODES;

    // ---- A prefetch depth 4 (independent of precompute; runs under PDL) ----
    float fa[4][4];
    #pragma unroll
    for (int p = 0; p < 4; p++) {
        size_t o = (size_t)(p * 8) * N_NODES;
        fa[p][0] = pa[o];
        fa[p][1] = pa[o + 8];
        fa[p][2] = pa[o + N4];
        fa[p][3] = pa[o + N4 + 8];
    }

    cudaGridDependencySynchronize();

    // B fragment pointer for this k-group (ksteps kg*16 .. kg*16+15)
    const float4* pb = g_Bfrag + (size_t)(kg * 16 * 4) * 32 + lane;
    float4 fbA[4], fbB[4];
    #pragma unroll
    for (int nt = 0; nt < 4; nt++) {
        fbA[nt] = pb[(0 * 4 + nt) << 5];
        fbB[nt] = pb[(1 * 4 + nt) << 5];
    }

    float acc[4][4];
    #pragma unroll
    for (int i = 0; i < 4; i++)
        #pragma unroll
        for (int k = 0; k < 4; k++) acc[i][k] = 0.f;

    #define STEP(u, FB) {                                                         \
        const int ks = it + (u);                                                  \
        unsigned ah[4], al[4];                                                    \
        _Pragma("unroll")                                                         \
        for (int i = 0; i < 4; i++) {                                             \
            float av = fa[u][i];                                                  \
            asm("cvt.rna.tf32.f32 %0, %1;" : "=r"(ah[i]) : "f"(av));              \
            float lo = av - __uint_as_float(ah[i]);                               \
            asm("cvt.rna.tf32.f32 %0, %1;" : "=r"(al[i]) : "f"(lo));              \
        }                                                                         \
        {                                                                         \
            size_t o = (size_t)((((ks) + 4) & 15) * 8) * N_NODES;                 \
            fa[u][0] = pa[o];                                                     \
            fa[u][1] = pa[o + 8];                                                 \
            fa[u][2] = pa[o + N4];                                                \
            fa[u][3] = pa[o + N4 + 8];                                            \
        }                                                                         \
        _Pragma("unroll")                                                         \
        for (int nt = 0; nt < 4; nt++) {                                          \
            unsigned b0h = __float_as_uint(FB[nt].x);                             \
            unsigned b1h = __float_as_uint(FB[nt].y);                             \
            unsigned b0l = __float_as_uint(FB[nt].z);                             \
            unsigned b1l = __float_as_uint(FB[nt].w);                             \
            MMA(acc[nt], ah[0], ah[1], ah[2], ah[3], b0h, b1h);                   \
            MMA(acc[nt], ah[0], ah[1], ah[2], ah[3], b0l, b1l);                   \
            MMA(acc[nt], al[0], al[1], al[2], al[3], b0h, b1h);                   \
        }                                                                         \
        _Pragma("unroll")                                                         \
        for (int nt = 0; nt < 4; nt++)                                            \
            FB[nt] = pb[(((((ks) + 2) & 15) * 4 + nt) << 5)];                     \
    }

    for (int it = 0; it < 16; it += 4) {
        STEP(0, fbA)
        STEP(1, fbB)
        STEP(2, fbA)
        STEP(3, fbB)
    }
    #undef STEP

    // ---- merge k-groups ----
    if (kg == 1) {
        #pragma unroll
        for (int nt = 0; nt < 4; nt++)
            #pragma unroll
            for (int i = 0; i < 4; i++)
                red[rtile][lane][nt * 4 + i] = acc[nt][i];
    }
    __syncthreads();

    if (kg == 0) {
        #pragma unroll
        for (int nt = 0; nt < 4; nt++)
            #pragma unroll
            for (int i = 0; i < 4; i++)
                acc[nt][i] += red[rtile][lane][nt * 4 + i];

        const int r0 = n0 + (lane >> 2);
        #pragma unroll
        for (int nt = 0; nt < 4; nt++) {
            int col = nt * 8 + 2 * (lane & 3);
            float2 cc = *(const float2*)(g_c + col);
            float2 v0 = make_float2(acc[nt][0] + cc.x, acc[nt][1] + cc.y);
            float2 v1 = make_float2(acc[nt][2] + cc.x, acc[nt][3] + cc.y);
            *(float2*)(out + (size_t)r0 * D_LAT + col)       = v0;
            *(float2*)(out + (size_t)(r0 + 8) * D_LAT + col) = v1;
        }
    }
}

extern "C" void kernel_launch(void* const* d_in, const int* in_sizes, int n_in,
                              void* d_out, int out_size)
{
    const float* embeds     = (const float*)d_in[0];
    const float* dists      = (const float*)d_in[1];
    const float* W_hidden   = (const float*)d_in[2];
    const float* b_hidden   = (const float*)d_in[3];
    const int*   anchor_ids = (const int*)  d_in[4];
    float*       out        = (float*)d_out;

    precompute_kernel<<<9, 256>>>(embeds, W_hidden, b_hidden, anchor_ids);

    cudaLaunchConfig_t cfg = {};
    cfg.gridDim  = dim3(N_NODES / 64, 1, 1);
    cfg.blockDim = dim3(256, 1, 1);
    cfg.dynamicSmemBytes = 0;
    cfg.stream = 0;
    cudaLaunchAttribute attr[1];
    attr[0].id = cudaLaunchAttributeProgrammaticStreamSerialization;
    attr[0].val.programmaticStreamSerializationAllowed = 1;
    cfg.attrs = attr;
    cfg.numAttrs = 1;

    cudaError_t e = cudaLaunchKernelEx(&cfg, pnn_mma_kernel, dists, out);
    if (e != cudaSuccess) {
        pnn_mma_kernel<<<N_NODES / 64, 256>>>(dists, out);
    }
}

// round 12
// speedup vs baseline: 1.1530x; 1.1056x over previous
#include <cuda_runtime.h>
#include <cstdint>

#define N_NODES 16384
#define A_ANCH  256
#define D_LAT   32

// B fragments for mma.m16n8k8.tf32, fragment order, pre-split hi/lo:
//   g_Bfrag[((ks*4 + nt)*32 + lane)] = (b0_hi, b1_hi, b0_lo, b1_lo)
// b0 = Mscaled[ks*8 + lane%4][nt*8 + lane/4], b1 = +4 k-row.
__device__ float4 g_Bfrag[32 * 4 * 32];   // 64 KB
__device__ float  g_c[D_LAT];

// ---------------------------------------------------------------------------
// Kernel 1: precompute B fragments + c (validated).
// ---------------------------------------------------------------------------
__global__ __launch_bounds__(256) void precompute_kernel(
    const float* __restrict__ embeds,
    const float* __restrict__ W,
    const float* __restrict__ b,
    const int*   __restrict__ anchor_ids)
{
    __shared__ float Wsh[D_LAT * D_LAT];
    __shared__ float esh[32][32];
    __shared__ float Ms[32][33];
    __shared__ float ssh[D_LAT];

    const int t   = threadIdx.x;
    const int blk = blockIdx.x;
    const int j   = t & 31;

    if (blk < 8) {
        #pragma unroll
        for (int i = t; i < D_LAT * D_LAT; i += 256) Wsh[i] = W[i];
        for (int r = t >> 5; r < 32; r += 8) {
            int id = anchor_ids[blk * 32 + r];
            esh[r][j] = embeds[id * D_LAT + j];
        }
        __syncthreads();
        for (int r = t >> 5; r < 32; r += 8) {
            float acc = 0.f;
            #pragma unroll
            for (int d = 0; d < D_LAT; d++) acc += esh[r][d] * Wsh[d * D_LAT + j];
            Ms[r][j] = acc * (1.0f / 256.0f);
        }
        __syncthreads();
        #pragma unroll
        for (int i = 0; i < 2; i++) {
            int idx  = t + 256 * i;
            int lane = idx & 31;
            int nt   = (idx >> 5) & 3;
            int kl   = (idx >> 7) & 3;
            int krow = kl * 8 + (lane & 3);
            int col  = nt * 8 + (lane >> 2);
            float b0 = Ms[krow][col];
            float b1 = Ms[krow + 4][col];
            unsigned h0, h1, l0, l1;
            asm("cvt.rna.tf32.f32 %0, %1;" : "=r"(h0) : "f"(b0));
            asm("cvt.rna.tf32.f32 %0, %1;" : "=r"(h1) : "f"(b1));
            float r0 = b0 - __uint_as_float(h0);
            float r1 = b1 - __uint_as_float(h1);
            asm("cvt.rna.tf32.f32 %0, %1;" : "=r"(l0) : "f"(r0));
            asm("cvt.rna.tf32.f32 %0, %1;" : "=r"(l1) : "f"(r1));
            int ks = blk * 4 + kl;
            g_Bfrag[(ks * 4 + nt) * 32 + lane] =
                make_float4(__uint_as_float(h0), __uint_as_float(h1),
                            __uint_as_float(l0), __uint_as_float(l1));
        }
    } else {
        #pragma unroll
        for (int i = t; i < D_LAT * D_LAT; i += 256) Wsh[i] = W[D_LAT * D_LAT + i];
        if (t < D_LAT) ssh[t] = 0.f;
        __syncthreads();
        {
            int grp = t >> 5;
            float part = 0.f;
            #pragma unroll 4
            for (int i = 0; i < 32; i++)
                part += embeds[(grp * 32 + i) * D_LAT + j];
            atomicAdd(&ssh[j], part);
        }
        __syncthreads();
        if (t < D_LAT) {
            float acc = 0.f;
            #pragma unroll
            for (int d = 0; d < D_LAT; d++) acc += ssh[d] * Wsh[d * D_LAT + t];
            g_c[t] = b[t] + acc * (1.0f / 256.0f);
        }
    }
}

// ---------------------------------------------------------------------------
// Kernel 2: tensor GEMM out = dists^T @ M + c, mma.m16n8k8.tf32, 3-term split.
// 256 thr = 8 warps = 2 row-tiles (16 rows) x 4 k-groups (64 k = 8 ksteps).
// Block covers 32 rows; grid 512 -> ~3 blocks/SM (24 warps/SM).
// K-group partials merged via 12 KB smem; kg0 warps do the epilogue.
// ---------------------------------------------------------------------------
#define MMA(AC, A0, A1, A2, A3, B0, B1)                                       \
    asm("mma.sync.aligned.m16n8k8.row.col.f32.tf32.tf32.f32 "                 \
        "{%0,%1,%2,%3},{%4,%5,%6,%7},{%8,%9},{%0,%1,%2,%3};"                  \
        : "+f"(AC[0]), "+f"(AC[1]), "+f"(AC[2]), "+f"(AC[3])                  \
        : "r"(A0), "r"(A1), "r"(A2), "r"(A3), "r"(B0), "r"(B1));

__global__ __launch_bounds__(256) void pnn_mma_kernel(
    const float* __restrict__ dists,   // [A, N]
    float*       __restrict__ out)     // [N, 32]
{
    __shared__ float red[3][2][32][16];   // 12 KB: k-groups 1..3 partials

    const int t     = threadIdx.x;
    const int lane  = t & 31;
    const int w     = t >> 5;
    const int rtile = w & 1;
    const int kg    = w >> 1;          // 0..3
    const int n0    = blockIdx.x * 32 + rtile * 16;

    const int rowA = n0 + (lane >> 2);
    const int colA = lane & 3;
    // k-group kg covers global k rows [kg*64, kg*64+64) -> 8 ksteps
    const float* pa = dists + (size_t)(kg * 64 + colA) * N_NODES + rowA;
    const size_t N4 = 4 * (size_t)N_NODES;

    // ---- A prefetch depth 4 (runs under PDL, before grid sync) ----
    float fa[4][4];
    #pragma unroll
    for (int p = 0; p < 4; p++) {
        size_t o = (size_t)(p * 8) * N_NODES;
        fa[p][0] = pa[o];
        fa[p][1] = pa[o + 8];
        fa[p][2] = pa[o + N4];
        fa[p][3] = pa[o + N4 + 8];
    }

    cudaGridDependencySynchronize();

    // B fragments for this k-group (ksteps kg*8 .. kg*8+7)
    const float4* pb = g_Bfrag + (size_t)(kg * 8 * 4) * 32 + lane;
    float4 fbA[4], fbB[4];
    #pragma unroll
    for (int nt = 0; nt < 4; nt++) {
        fbA[nt] = pb[(0 * 4 + nt) << 5];
        fbB[nt] = pb[(1 * 4 + nt) << 5];
    }

    float acc[4][4];
    #pragma unroll
    for (int i = 0; i < 4; i++)
        #pragma unroll
        for (int k = 0; k < 4; k++) acc[i][k] = 0.f;

    #define STEP(u, FB) {                                                         \
        const int ks = it + (u);                                                  \
        unsigned ah[4], al[4];                                                    \
        _Pragma("unroll")                                                         \
        for (int i = 0; i < 4; i++) {                                             \
            float av = fa[u][i];                                                  \
            asm("cvt.rna.tf32.f32 %0, %1;" : "=r"(ah[i]) : "f"(av));              \
            float lo = av - __uint_as_float(ah[i]);                               \
            asm("cvt.rna.tf32.f32 %0, %1;" : "=r"(al[i]) : "f"(lo));              \
        }                                                                         \
        if (ks + 4 < 8) {                                                         \
            size_t o = (size_t)((ks + 4) * 8) * N_NODES;                          \
            fa[u][0] = pa[o];                                                     \
            fa[u][1] = pa[o + 8];                                                 \
            fa[u][2] = pa[o + N4];                                                \
            fa[u][3] = pa[o + N4 + 8];                                            \
        }                                                                         \
        _Pragma("unroll")                                                         \
        for (int nt = 0; nt < 4; nt++) {                                          \
            unsigned b0h = __float_as_uint(FB[nt].x);                             \
            unsigned b1h = __float_as_uint(FB[nt].y);                             \
            unsigned b0l = __float_as_uint(FB[nt].z);                             \
            unsigned b1l = __float_as_uint(FB[nt].w);                             \
            MMA(acc[nt], ah[0], ah[1], ah[2], ah[3], b0h, b1h);                   \
            MMA(acc[nt], ah[0], ah[1], ah[2], ah[3], b0l, b1l);                   \
            MMA(acc[nt], al[0], al[1], al[2], al[3], b0h, b1h);                   \
        }                                                                         \
        if (ks + 2 < 8) {                                                         \
            _Pragma("unroll")                                                     \
            for (int nt = 0; nt < 4; nt++)                                        \
                FB[nt] = pb[(((ks + 2) * 4 + nt) << 5)];                          \
        }                                                                         \
    }

    #pragma unroll
    for (int it = 0; it < 8; it += 4) {
        STEP(0, fbA)
        STEP(1, fbB)
        STEP(2, fbA)
        STEP(3, fbB)
    }
    #undef STEP

    // ---- merge the 4 k-groups ----
    if (kg != 0) {
        #pragma unroll
        for (int nt = 0; nt < 4; nt++)
            #pragma unroll
            for (int i = 0; i < 4; i++)
                red[kg - 1][rtile][lane][nt * 4 + i] = acc[nt][i];
    }
    __syncthreads();

    if (kg == 0) {
        #pragma unroll
        for (int g = 0; g < 3; g++)
            #pragma unroll
            for (int nt = 0; nt < 4; nt++)
                #pragma unroll
                for (int i = 0; i < 4; i++)
                    acc[nt][i] += red[g][rtile][lane][nt * 4 + i];

        const int r0 = n0 + (lane >> 2);
        #pragma unroll
        for (int nt = 0; nt < 4; nt++) {
            int col = nt * 8 + 2 * (lane & 3);
            float2 cc = *(const float2*)(g_c + col);
            float2 v0 = make_float2(acc[nt][0] + cc.x, acc[nt][1] + cc.y);
            float2 v1 = make_float2(acc[nt][2] + cc.x, acc[nt][3] + cc.y);
            *(float2*)(out + (size_t)r0 * D_LAT + col)       = v0;
            *(float2*)(out + (size_t)(r0 + 8) * D_LAT + col) = v1;
        }
    }
}

extern "C" void kernel_launch(void* const* d_in, const int* in_sizes, int n_in,
                              void* d_out, int out_size)
{
    const float* embeds     = (const float*)d_in[0];
    const float* dists      = (const float*)d_in[1];
    const float* W_hidden   = (const float*)d_in[2];
    const float* b_hidden   = (const float*)d_in[3];
    const int*   anchor_ids = (const int*)  d_in[4];
    float*       out        = (float*)d_out;

    precompute_kernel<<<9, 256>>>(embeds, W_hidden, b_hidden, anchor_ids);

    cudaLaunchConfig_t cfg = {};
    cfg.gridDim  = dim3(N_NODES / 32, 1, 1);
    cfg.blockDim = dim3(256, 1, 1);
    cfg.dynamicSmemBytes = 0;
    cfg.stream = 0;
    cudaLaunchAttribute attr[1];
    attr[0].id = cudaLaunchAttributeProgrammaticStreamSerialization;
    attr[0].val.programmaticStreamSerializationAllowed = 1;
    cfg.attrs = attr;
    cfg.numAttrs = 1;

    cudaError_t e = cudaLaunchKernelEx(&cfg, pnn_mma_kernel, dists, out);
    if (e != cudaSuccess) {
        pnn_mma_kernel<<<N_NODES / 32, 256>>>(dists, out);
    }
}